// round 4
// baseline (speedup 1.0000x reference)
#include <cuda_runtime.h>
#include <cstdint>

// Fixed problem shapes
constexpr int B_ = 32, N_ = 128, K_ = 16, F_ = 256, D_ = 256;
constexpr int ATOMS = 4;                 // atoms per CTA
constexpr int ROWS = ATOMS * K_;         // 64 neighbor GEMM rows
constexpr int THREADS = 256;             // 8 warps
constexpr int TF = 16;                   // F per stage
constexpr int NST = F_ / TF;             // 16 stages

constexpr int PADA = 264;                // nb / C row stride (floats)
constexpr int WPS  = 520;                // W-tile plane stride (floats)

// shared layout (floats)
constexpr int OFF_NB  = 0;                        // 72 rows x 264: nb rows 0..63, x rows 64..71 (later C / af)
constexpr int OFF_WN  = OFF_NB + 72 * PADA;       // 8 planes x 520
constexpr int OFF_WAT = OFF_WN + 8 * WPS;         // 8 planes x 520
constexpr int OFF_SM  = OFF_WAT + 8 * WPS;        // 64
constexpr int OFF_AM  = OFF_SM + ROWS;            // 64
constexpr int OFF_RED = OFF_AM + ROWS;            // 8 warps x 16
constexpr int OFF_LN  = OFF_RED + 128;            // 16
constexpr int SMEM_FL = OFF_LN + 16;              // 27600 floats = 110,400 B -> 2 CTAs/SM

__device__ __forceinline__ float to_tf32(float x) {
    float y;
    asm("cvt.rna.tf32.f32 %0, %1;" : "=f"(y) : "f"(x));
    return y;
}

__device__ __forceinline__ void mma_tf32(float c[4], uint32_t a0, uint32_t a1,
                                         uint32_t a2, uint32_t a3,
                                         uint32_t b0, uint32_t b1) {
    asm volatile(
        "mma.sync.aligned.m16n8k8.row.col.f32.tf32.tf32.f32 "
        "{%0,%1,%2,%3},{%4,%5,%6,%7},{%8,%9},{%0,%1,%2,%3};"
        : "+f"(c[0]), "+f"(c[1]), "+f"(c[2]), "+f"(c[3])
        : "r"(a0), "r"(a1), "r"(a2), "r"(a3), "r"(b0), "r"(b1));
}

__global__ void __launch_bounds__(THREADS, 2)
gnn_atom_aggregate_kernel(const float* __restrict__ atom_feat,
                          const float* __restrict__ nbr_feat,
                          const float* __restrict__ smask,
                          const float* __restrict__ amask,
                          const float* __restrict__ Wa,
                          const float* __restrict__ ba,
                          const float* __restrict__ Wn,
                          const float* __restrict__ bn,
                          const float* __restrict__ wal,
                          const float* __restrict__ bal,
                          const float* __restrict__ gam,
                          const float* __restrict__ bet,
                          float* __restrict__ out)
{
    extern __shared__ float s[];
    const int tid  = threadIdx.x;
    const int blk  = blockIdx.x;
    const int lane = tid & 31;
    const int w    = tid >> 5;
    const int l4   = lane & 3;
    const int lr   = lane >> 2;

    // ---- prologue: pack nb + x rows (tf32, (f,f+4)-pair layout) + masks ----
    {
        const float4* nb_src = (const float4*)(nbr_feat + (size_t)blk * ROWS * F_);
#pragma unroll
        for (int i = 0; i < 16; i++) {
            int ft  = tid + i * THREADS;        // float4 id, 4096 total
            int row = ft >> 6;
            int c4  = ft & 63;
            float4 v = nb_src[ft];
            float* base = s + OFF_NB + row * PADA + (c4 >> 1) * 8 + (c4 & 1);
            base[0] = to_tf32(v.x); base[2] = to_tf32(v.y);
            base[4] = to_tf32(v.z); base[6] = to_tf32(v.w);
        }
        // atom features as rows 64..67 (same packed layout)
        {
            float4 v = ((const float4*)(atom_feat + (size_t)blk * ATOMS * F_))[tid];
            int row = 64 + (tid >> 6);
            int c4  = tid & 63;
            float* base = s + OFF_NB + row * PADA + (c4 >> 1) * 8 + (c4 & 1);
            base[0] = to_tf32(v.x); base[2] = to_tf32(v.y);
            base[4] = to_tf32(v.z); base[6] = to_tf32(v.w);
        }
        // zero pad rows 68..71 (read by af A-fragments)
#pragma unroll
        for (int i = 0; i < 5; i++) {
            int idx = tid + i * THREADS;
            if (idx < 4 * PADA) s[OFF_NB + 68 * PADA + idx] = 0.f;
        }
        if (tid < 16)
            ((float4*)(s + OFF_SM))[tid] = ((const float4*)(smask + blk * ROWS))[tid];
        else if (tid < 32)
            ((float4*)(s + OFF_AM))[tid - 16] = ((const float4*)(amask + blk * ROWS))[tid - 16];
    }

    // W streaming: thread covers d = tid, all 16 f's of the stage
    float cwn[16], cwa[16];
    {
        const float4* pn = (const float4*)(Wn + (size_t)tid * F_);
        const float4* pa = (const float4*)(Wa + (size_t)tid * F_);
#pragma unroll
        for (int q = 0; q < 4; q++) {
            *(float4*)(cwn + q * 4) = pn[q];
            *(float4*)(cwa + q * 4) = pa[q];
        }
    }

    float acc[2][8][4];
#pragma unroll
    for (int rf = 0; rf < 2; rf++)
#pragma unroll
        for (int j = 0; j < 8; j++)
#pragma unroll
            for (int q = 0; q < 4; q++) acc[rf][j][q] = 0.f;
    float afc[4][4];
#pragma unroll
    for (int u = 0; u < 4; u++)
#pragma unroll
        for (int q = 0; q < 4; q++) afc[u][q] = 0.f;

    const int rb = w >> 2;     // row block (32 rows)
    const int cb = w & 3;      // col block (64 cols)

    // ---- main loop ----
    for (int st = 0; st < NST; st++) {
        __syncthreads();   // previous-stage W-tile reads complete
        // store W tiles: plane p holds (B[f][d], B[f+4][d]); d = tid -> contiguous, conflict-free
#pragma unroll
        for (int p = 0; p < 8; p++) {
            int fl = (p >> 2) * 8 + (p & 3);
            *(float2*)(s + OFF_WN + p * WPS + tid * 2)
                = make_float2(to_tf32(cwn[fl]), to_tf32(cwn[fl + 4]));
            *(float2*)(s + OFF_WAT + p * WPS + tid * 2)
                = make_float2(to_tf32(cwa[fl]), to_tf32(cwa[fl + 4]));
        }
        __syncthreads();
        // prefetch next stage W rows (overlaps with MMAs below)
        if (st + 1 < NST) {
            const float4* pn = (const float4*)(Wn + (size_t)tid * F_ + (st + 1) * TF);
            const float4* pa = (const float4*)(Wa + (size_t)tid * F_ + (st + 1) * TF);
#pragma unroll
            for (int q = 0; q < 4; q++) {
                *(float4*)(cwn + q * 4) = pn[q];
                *(float4*)(cwa + q * 4) = pa[q];
            }
        }

#pragma unroll
        for (int kk = 0; kk < 2; kk++) {
            const int g = st * 2 + kk;
            const float* nbb = s + OFF_NB + g * 8 + l4 * 2;
            float2 a02_0 = *(const float2*)(nbb + (rb * 32 + lr) * PADA);
            float2 a13_0 = *(const float2*)(nbb + (rb * 32 + 8 + lr) * PADA);
            float2 a02_1 = *(const float2*)(nbb + (rb * 32 + 16 + lr) * PADA);
            float2 a13_1 = *(const float2*)(nbb + (rb * 32 + 24 + lr) * PADA);
            float2 afa   = *(const float2*)(nbb + (64 + lr) * PADA);
            const float* wnp = s + OFF_WN  + (kk * 4 + l4) * WPS + lr * 2;
            const float* wap = s + OFF_WAT + (kk * 4 + l4) * WPS + lr * 2;
#pragma unroll
            for (int j = 0; j < 8; j++) {
                float2 b = *(const float2*)(wnp + (cb * 64 + j * 8) * 2);
                mma_tf32(acc[0][j],
                         __float_as_uint(a02_0.x), __float_as_uint(a13_0.x),
                         __float_as_uint(a02_0.y), __float_as_uint(a13_0.y),
                         __float_as_uint(b.x), __float_as_uint(b.y));
                mma_tf32(acc[1][j],
                         __float_as_uint(a02_1.x), __float_as_uint(a13_1.x),
                         __float_as_uint(a02_1.y), __float_as_uint(a13_1.y),
                         __float_as_uint(b.x), __float_as_uint(b.y));
            }
            // af GEMM: warp covers col frags w*4+u; A rows 8..15 are zero operands
#pragma unroll
            for (int u = 0; u < 4; u++) {
                float2 b = *(const float2*)(wap + ((w * 4 + u) * 8) * 2);
                mma_tf32(afc[u],
                         __float_as_uint(afa.x), 0u,
                         __float_as_uint(afa.y), 0u,
                         __float_as_uint(b.x), __float_as_uint(b.y));
            }
        }
    }

    __syncthreads();   // all MMA reads of nb done before overwriting with C

    // ---- write C (nf rows 0..63) and af (rows 64..71) to smem, raw col layout ----
    {
        float* nf = s + OFF_NB;
#pragma unroll
        for (int rf = 0; rf < 2; rf++) {
            int r0 = rb * 32 + rf * 16 + lr;
#pragma unroll
            for (int j = 0; j < 8; j++) {
                int col = cb * 64 + j * 8 + 2 * l4;
                *(float2*)(nf + r0 * PADA + col)       = make_float2(acc[rf][j][0], acc[rf][j][1]);
                *(float2*)(nf + (r0 + 8) * PADA + col) = make_float2(acc[rf][j][2], acc[rf][j][3]);
            }
        }
#pragma unroll
        for (int u = 0; u < 4; u++) {
            int col = (w * 4 + u) * 8 + 2 * l4;
            *(float2*)(nf + (64 + lr) * PADA + col) = make_float2(afc[u][0], afc[u][1]);
        }
    }
    __syncthreads();

    // ---- epilogue: score -> softmax -> ctx -> LayerNorm ----
    const int dd = tid;                 // output feature
    const float ba_d  = ba[dd];
    const float bn_d  = bn[dd];
    const float wal_d = wal[dd & 63];
    const float bal_s = bal[0];
    const float g_d   = gam[dd];
    const float be_d  = bet[dd];
    const int   h     = dd >> 6;        // head
    float* s_red = s + OFF_RED;
    float* s_ln  = s + OFF_LN;
    const float* s_sm = s + OFF_SM;
    const float* s_am = s + OFF_AM;
    const float* nf   = s + OFF_NB;

#pragma unroll
    for (int atom = 0; atom < ATOMS; atom++) {
        const float afv = nf[(64 + atom) * PADA + dd] + ba_d;
        float nfr[K_], pp[K_];
#pragma unroll
        for (int k = 0; k < K_; k++) {
            nfr[k] = nf[(atom * 16 + k) * PADA + dd] + bn_d;
            float t = afv + nfr[k];
            t = (t > 0.f) ? t : 0.2f * t;      // leaky relu
            pp[k] = t * wal_d;
        }
#pragma unroll
        for (int off = 16; off; off >>= 1) {
#pragma unroll
            for (int k = 0; k < K_; k++)
                pp[k] += __shfl_xor_sync(0xffffffffu, pp[k], off);
        }
        if (lane == 0) {
#pragma unroll
            for (int k = 0; k < K_; k++) s_red[w * 16 + k] = pp[k];
        }
        __syncthreads();

        float sc[K_];
        float mx = -3.4e38f;
#pragma unroll
        for (int k = 0; k < K_; k++) {
            sc[k] = s_red[(2 * h) * 16 + k] + s_red[(2 * h + 1) * 16 + k]
                  + bal_s + s_sm[atom * 16 + k];
            mx = fmaxf(mx, sc[k]);
        }
        float ssum = 0.f;
#pragma unroll
        for (int k = 0; k < K_; k++) { sc[k] = __expf(sc[k] - mx); ssum += sc[k]; }
        float inv = 1.f / ssum;
        float ctx = 0.f;
#pragma unroll
        for (int k = 0; k < K_; k++)
            ctx = fmaf(sc[k] * inv * s_am[atom * 16 + k], nfr[k], ctx);

        float s1 = ctx, s2 = ctx * ctx;
#pragma unroll
        for (int off = 16; off; off >>= 1) {
            s1 += __shfl_xor_sync(0xffffffffu, s1, off);
            s2 += __shfl_xor_sync(0xffffffffu, s2, off);
        }
        if (lane == 0) { s_ln[w] = s1; s_ln[8 + w] = s2; }
        __syncthreads();
        float S1 = 0.f, S2 = 0.f;
#pragma unroll
        for (int q = 0; q < 8; q++) { S1 += s_ln[q]; S2 += s_ln[8 + q]; }
        float mu  = S1 * (1.f / 256.f);
        float var = S2 * (1.f / 256.f) - mu * mu;
        float o = (ctx - mu) * rsqrtf(var + 1e-5f) * g_d + be_d;
        out[(size_t)(blk * ATOMS + atom) * D_ + dd] = o;
        __syncthreads();
    }
}

extern "C" void kernel_launch(void* const* d_in, const int* in_sizes, int n_in,
                              void* d_out, int out_size)
{
    const float* atom_feat = (const float*)d_in[0];
    const float* nbr_feat  = (const float*)d_in[1];
    const float* smask     = (const float*)d_in[2];
    const float* amask     = (const float*)d_in[3];
    const float* Wa        = (const float*)d_in[4];
    const float* ba        = (const float*)d_in[5];
    const float* Wn        = (const float*)d_in[6];
    const float* bn        = (const float*)d_in[7];
    const float* wal       = (const float*)d_in[8];
    const float* bal       = (const float*)d_in[9];
    const float* gam       = (const float*)d_in[10];
    const float* bet       = (const float*)d_in[11];
    float* out = (float*)d_out;

    cudaFuncSetAttribute(gnn_atom_aggregate_kernel,
                         cudaFuncAttributeMaxDynamicSharedMemorySize,
                         SMEM_FL * (int)sizeof(float));

    gnn_atom_aggregate_kernel<<<(B_ * N_) / ATOMS, THREADS,
                                SMEM_FL * sizeof(float)>>>(
        atom_feat, nbr_feat, smask, amask, Wa, ba, Wn, bn, wal, bal, gam, bet, out);
}

// round 5
// speedup vs baseline: 2.4792x; 2.4792x over previous
#include <cuda_runtime.h>
#include <cstdint>

// Fixed problem shapes
constexpr int B_ = 32, N_ = 128, K_ = 16, F_ = 256, D_ = 256;
constexpr int NF_ROWS = B_ * N_ * K_;   // 65536
constexpr int AF_ROWS = B_ * N_;        // 4096
constexpr int NF_TILES = NF_ROWS / 128; // 512
constexpr int AF_TILES = AF_ROWS / 128; // 32

// scratch (device globals: allowed)
__device__ float g_nf[NF_ROWS * D_];
__device__ float g_af[AF_ROWS * D_];

// ---------------- GEMM kernel ----------------
constexpr int GT   = 512;   // threads (16 warps)
constexpr int SA   = 36;    // A smem row stride (floats); lane bank = lr*4+l4 -> conflict-free
constexpr int SB   = 36;    // B smem row stride
constexpr int CH   = 32;    // K chunk
constexpr int NCH  = F_ / CH; // 8
constexpr int STG  = 4;     // pipeline stages
constexpr int OFF_A = 0;                    // STG * 128 * SA
constexpr int OFF_B = STG * 128 * SA;       // STG * 256 * SB
constexpr int GSMEM = OFF_B + STG * 256 * SB;   // 55296 floats = 221184 B

__device__ __forceinline__ uint32_t s2u(const void* p) {
    return static_cast<uint32_t>(__cvta_generic_to_shared(p));
}
__device__ __forceinline__ void cp16(uint32_t dst, const void* src) {
    asm volatile("cp.async.cg.shared.global [%0], [%1], 16;\n" :: "r"(dst), "l"(src));
}
__device__ __forceinline__ uint32_t tf32u(float x) {
    float y;
    asm("cvt.rna.tf32.f32 %0, %1;" : "=f"(y) : "f"(x));
    return __float_as_uint(y);
}
__device__ __forceinline__ void mma_tf32(float c[4], uint32_t a0, uint32_t a1,
                                         uint32_t a2, uint32_t a3,
                                         uint32_t b0, uint32_t b1) {
    asm volatile(
        "mma.sync.aligned.m16n8k8.row.col.f32.tf32.tf32.f32 "
        "{%0,%1,%2,%3},{%4,%5,%6,%7},{%8,%9},{%0,%1,%2,%3};"
        : "+f"(c[0]), "+f"(c[1]), "+f"(c[2]), "+f"(c[3])
        : "r"(a0), "r"(a1), "r"(a2), "r"(a3), "r"(b0), "r"(b1));
}

__global__ void __launch_bounds__(GT, 1)
gemm_kernel(const float* __restrict__ nbr,
            const float* __restrict__ atom,
            const float* __restrict__ Wn,
            const float* __restrict__ Wa)
{
    extern __shared__ float s[];
    const int tid = threadIdx.x;
    const int blk = blockIdx.x;
    const bool is_af = (blk >= NF_TILES);
    const float* Ag = is_af ? atom : nbr;
    const float* Wg = is_af ? Wa : Wn;
    float* Cg       = is_af ? g_af : g_nf;
    const int row0  = (is_af ? (blk - NF_TILES) : blk) * 128;

    // issue one K-chunk (A: 128x32, B: 256x32) into stage c%STG
    auto issue = [&](int c) {
        const int sb = c % STG;
#pragma unroll
        for (int i = 0; i < 2; i++) {           // A: 1024 cp16
            int idx = tid + i * GT;
            int r = idx >> 3, q = idx & 7;
            cp16(s2u(s + OFF_A + (sb * 128 + r) * SA + q * 4),
                 Ag + (size_t)(row0 + r) * F_ + c * CH + q * 4);
        }
#pragma unroll
        for (int i = 0; i < 4; i++) {           // B: 2048 cp16
            int idx = tid + i * GT;
            int d = idx >> 3, q = idx & 7;
            cp16(s2u(s + OFF_B + (sb * 256 + d) * SB + q * 4),
                 Wg + (size_t)d * F_ + c * CH + q * 4);
        }
    };

    issue(0); asm volatile("cp.async.commit_group;\n");
    issue(1); asm volatile("cp.async.commit_group;\n");
    issue(2); asm volatile("cp.async.commit_group;\n");

    const int lane = tid & 31;
    const int w    = tid >> 5;
    const int l4   = lane & 3;
    const int lr   = lane >> 2;
    const int rb   = w >> 2;     // row block (32 rows)
    const int cb   = w & 3;      // col block (64 cols)

    float acc[2][8][4];
#pragma unroll
    for (int rf = 0; rf < 2; rf++)
#pragma unroll
        for (int j = 0; j < 8; j++)
#pragma unroll
            for (int q = 0; q < 4; q++) acc[rf][j][q] = 0.f;

    for (int c = 0; c < NCH; c++) {
        asm volatile("cp.async.wait_group 2;\n");   // chunk c complete (this thread)
        __syncthreads();                            // ... and all threads
        if (c + 3 < NCH) issue(c + 3);
        asm volatile("cp.async.commit_group;\n");   // keep group count aligned

        const float* sa  = s + OFF_A + (c % STG) * 128 * SA;
        const float* sbb = s + OFF_B + (c % STG) * 256 * SB;

#pragma unroll
        for (int g = 0; g < 4; g++) {
            const int k0 = g * 8;
            uint32_t a[2][4];
#pragma unroll
            for (int rf = 0; rf < 2; rf++) {
                int r = rb * 32 + rf * 16 + lr;
                a[rf][0] = tf32u(sa[r * SA + k0 + l4]);
                a[rf][1] = tf32u(sa[(r + 8) * SA + k0 + l4]);
                a[rf][2] = tf32u(sa[r * SA + k0 + 4 + l4]);
                a[rf][3] = tf32u(sa[(r + 8) * SA + k0 + 4 + l4]);
            }
#pragma unroll
            for (int j = 0; j < 8; j++) {
                int cc = cb * 64 + j * 8 + lr;
                uint32_t b0 = tf32u(sbb[cc * SB + k0 + l4]);
                uint32_t b1 = tf32u(sbb[cc * SB + k0 + 4 + l4]);
                mma_tf32(acc[0][j], a[0][0], a[0][1], a[0][2], a[0][3], b0, b1);
                mma_tf32(acc[1][j], a[1][0], a[1][1], a[1][2], a[1][3], b0, b1);
            }
        }
        __syncthreads();   // all reads of stage c%STG done before it is refilled
    }

    // store C tile
#pragma unroll
    for (int rf = 0; rf < 2; rf++) {
        int r0 = row0 + rb * 32 + rf * 16 + lr;
#pragma unroll
        for (int j = 0; j < 8; j++) {
            int col = cb * 64 + j * 8 + 2 * l4;
            *(float2*)(Cg + (size_t)r0 * D_ + col)
                = make_float2(acc[rf][j][0], acc[rf][j][1]);
            *(float2*)(Cg + (size_t)(r0 + 8) * D_ + col)
                = make_float2(acc[rf][j][2], acc[rf][j][3]);
        }
    }
}

// ---------------- epilogue kernel ----------------
constexpr int ET = 256;          // thread = output feature d
constexpr int APC = 8;           // atoms per CTA

__global__ void __launch_bounds__(ET)
epi_kernel(const float* __restrict__ smask,
           const float* __restrict__ amask,
           const float* __restrict__ ba,
           const float* __restrict__ bn,
           const float* __restrict__ wal,
           const float* __restrict__ bal,
           const float* __restrict__ gam,
           const float* __restrict__ bet,
           float* __restrict__ out)
{
    __shared__ float s_sm[APC * K_];
    __shared__ float s_am[APC * K_];
    __shared__ float s_red[8 * K_];
    __shared__ float s_ln[16];

    const int tid  = threadIdx.x;
    const int blk  = blockIdx.x;
    const int lane = tid & 31;
    const int w    = tid >> 5;
    const int atom0 = blk * APC;

    if (tid < 128)       s_sm[tid] = smask[atom0 * K_ + tid];
    else                 s_am[tid - 128] = amask[atom0 * K_ + (tid - 128)];

    const int dd = tid;
    const float ba_d  = ba[dd];
    const float bn_d  = bn[dd];
    const float wal_d = wal[dd & 63];
    const float bal_s = bal[0];
    const float g_d   = gam[dd];
    const float be_d  = bet[dd];
    const int   h     = dd >> 6;
    __syncthreads();

#pragma unroll 2
    for (int a = 0; a < APC; a++) {
        const int atom = atom0 + a;
        const float afv = g_af[(size_t)atom * D_ + dd] + ba_d;
        float nfr[K_], pp[K_];
#pragma unroll
        for (int k = 0; k < K_; k++) {
            nfr[k] = g_nf[(size_t)(atom * K_ + k) * D_ + dd] + bn_d;
            float t = afv + nfr[k];
            t = (t > 0.f) ? t : 0.2f * t;      // leaky relu
            pp[k] = t * wal_d;
        }
#pragma unroll
        for (int off = 16; off; off >>= 1) {
#pragma unroll
            for (int k = 0; k < K_; k++)
                pp[k] += __shfl_xor_sync(0xffffffffu, pp[k], off);
        }
        if (lane == 0) {
#pragma unroll
            for (int k = 0; k < K_; k++) s_red[w * K_ + k] = pp[k];
        }
        __syncthreads();

        float sc[K_];
        float mx = -3.4e38f;
#pragma unroll
        for (int k = 0; k < K_; k++) {
            sc[k] = s_red[(2 * h) * K_ + k] + s_red[(2 * h + 1) * K_ + k]
                  + bal_s + s_sm[a * K_ + k];
            mx = fmaxf(mx, sc[k]);
        }
        float ssum = 0.f;
#pragma unroll
        for (int k = 0; k < K_; k++) { sc[k] = __expf(sc[k] - mx); ssum += sc[k]; }
        float inv = 1.f / ssum;
        float ctx = 0.f;
#pragma unroll
        for (int k = 0; k < K_; k++)
            ctx = fmaf(sc[k] * inv * s_am[a * K_ + k], nfr[k], ctx);

        float s1 = ctx, s2 = ctx * ctx;
#pragma unroll
        for (int off = 16; off; off >>= 1) {
            s1 += __shfl_xor_sync(0xffffffffu, s1, off);
            s2 += __shfl_xor_sync(0xffffffffu, s2, off);
        }
        if (lane == 0) { s_ln[w] = s1; s_ln[8 + w] = s2; }
        __syncthreads();
        float S1 = 0.f, S2 = 0.f;
#pragma unroll
        for (int q = 0; q < 8; q++) { S1 += s_ln[q]; S2 += s_ln[8 + q]; }
        float mu  = S1 * (1.f / 256.f);
        float var = S2 * (1.f / 256.f) - mu * mu;
        float o = (ctx - mu) * rsqrtf(var + 1e-5f) * g_d + be_d;
        out[(size_t)atom * D_ + dd] = o;
        __syncthreads();
    }
}

extern "C" void kernel_launch(void* const* d_in, const int* in_sizes, int n_in,
                              void* d_out, int out_size)
{
    const float* atom_feat = (const float*)d_in[0];
    const float* nbr_feat  = (const float*)d_in[1];
    const float* smask     = (const float*)d_in[2];
    const float* amask     = (const float*)d_in[3];
    const float* Wa        = (const float*)d_in[4];
    const float* ba        = (const float*)d_in[5];
    const float* Wn        = (const float*)d_in[6];
    const float* bn        = (const float*)d_in[7];
    const float* wal       = (const float*)d_in[8];
    const float* bal       = (const float*)d_in[9];
    const float* gam       = (const float*)d_in[10];
    const float* bet       = (const float*)d_in[11];
    float* out = (float*)d_out;

    cudaFuncSetAttribute(gemm_kernel,
                         cudaFuncAttributeMaxDynamicSharedMemorySize,
                         GSMEM * (int)sizeof(float));

    gemm_kernel<<<NF_TILES + AF_TILES, GT, GSMEM * sizeof(float)>>>(
        nbr_feat, atom_feat, Wn, Wa);
    epi_kernel<<<AF_ROWS / APC, ET>>>(
        smask, amask, ba, bn, wal, bal, gam, bet, out);
}

// round 6
// speedup vs baseline: 2.6529x; 1.0700x over previous
#include <cuda_runtime.h>
#include <cstdint>

// Fixed problem shapes
constexpr int B_ = 32, N_ = 128, K_ = 16, F_ = 256, D_ = 256;
constexpr int NF_ROWS = B_ * N_ * K_;   // 65536
constexpr int AF_ROWS = B_ * N_;        // 4096
constexpr int NF_TILES = NF_ROWS / 128; // 512
constexpr int AF_TILES = AF_ROWS / 128; // 32

__device__ float g_af[AF_ROWS * D_];    // af scratch (4 MB)

// ---------------- GEMM core config ----------------
constexpr int GT   = 512;    // 16 warps
constexpr int CH   = 64;     // K chunk (floats)
constexpr int NCH  = F_ / CH; // 4
constexpr int SROW = 68;     // smem row stride; lane bank = lr*4+l4 -> conflict-free
constexpr int OFF_A = 0;                      // 2 stages * 128 * 68
constexpr int OFF_B = 2 * 128 * SROW;         // 2 stages * 256 * 68
constexpr int GSMEM = OFF_B + 2 * 256 * SROW; // 52224 floats = 208896 B

// epilogue smem overlay (reuses GEMM smem after mainloop)
constexpr int E_AFB = 0;            // 8*256 af+ba
constexpr int E_BN  = E_AFB + 2048; // 256
constexpr int E_WAL = E_BN + 256;   // 64
constexpr int E_SC  = E_WAL + 64;   // 8*16*4 scores
constexpr int E_AW  = E_SC + 512;   // 8*16*4 attw
constexpr int E_SMK = E_AW + 512;   // 128
constexpr int E_AMK = E_SMK + 128;  // 128
constexpr int E_CTX = E_AMK + 128;  // 8*264
constexpr int E_LN  = E_CTX + 8 * 264; // 2*16

__device__ __forceinline__ uint32_t s2u(const void* p) {
    return static_cast<uint32_t>(__cvta_generic_to_shared(p));
}
__device__ __forceinline__ void cp16(uint32_t dst, const void* src) {
    asm volatile("cp.async.cg.shared.global [%0], [%1], 16;\n" :: "r"(dst), "l"(src));
}
__device__ __forceinline__ uint32_t tf32u(float x) {
    float y;
    asm("cvt.rna.tf32.f32 %0, %1;" : "=f"(y) : "f"(x));
    return __float_as_uint(y);
}
__device__ __forceinline__ void mma_tf32(float c[4], uint32_t a0, uint32_t a1,
                                         uint32_t a2, uint32_t a3,
                                         uint32_t b0, uint32_t b1) {
    asm volatile(
        "mma.sync.aligned.m16n8k8.row.col.f32.tf32.tf32.f32 "
        "{%0,%1,%2,%3},{%4,%5,%6,%7},{%8,%9},{%0,%1,%2,%3};"
        : "+f"(c[0]), "+f"(c[1]), "+f"(c[2]), "+f"(c[3])
        : "r"(a0), "r"(a1), "r"(a2), "r"(a3), "r"(b0), "r"(b1));
}

__device__ __forceinline__ void issue_chunk(float* s, const float* Ag,
                                            const float* Wg, int row0,
                                            int c, int tid) {
    const int sb = c & 1;
#pragma unroll
    for (int i = 0; i < 4; i++) {                 // A: 128x64 -> 2048 cp16
        int idx = tid + i * GT;
        int r = idx >> 4, q = idx & 15;
        cp16(s2u(s + OFF_A + (sb * 128 + r) * SROW + q * 4),
             Ag + (size_t)(row0 + r) * F_ + c * CH + q * 4);
    }
#pragma unroll
    for (int i = 0; i < 8; i++) {                 // B: 256x64 -> 4096 cp16
        int idx = tid + i * GT;
        int d = idx >> 4, q = idx & 15;
        cp16(s2u(s + OFF_B + (sb * 256 + d) * SROW + q * 4),
             Wg + (size_t)d * F_ + c * CH + q * 4);
    }
}

// GEMM mainloop: fills acc[2][8][4] for warp tile (rb*32 rows, cb*64 cols)
__device__ __forceinline__ void run_gemm(float* s, const float* Ag, const float* Wg,
                                         int row0, int tid, float acc[2][8][4]) {
    const int lane = tid & 31;
    const int w    = tid >> 5;
    const int l4   = lane & 3;
    const int lr   = lane >> 2;
    const int rb   = w >> 2;
    const int cb   = w & 3;

    issue_chunk(s, Ag, Wg, row0, 0, tid);
    asm volatile("cp.async.commit_group;\n");
    issue_chunk(s, Ag, Wg, row0, 1, tid);
    asm volatile("cp.async.commit_group;\n");

#pragma unroll
    for (int c = 0; c < NCH; c++) {
        if (c == NCH - 1) asm volatile("cp.async.wait_group 0;\n");
        else              asm volatile("cp.async.wait_group 1;\n");
        __syncthreads();

        const float* sa  = s + OFF_A + (c & 1) * 128 * SROW;
        const float* sbb = s + OFF_B + (c & 1) * 256 * SROW;
#pragma unroll
        for (int g = 0; g < 8; g++) {
            const int k0 = g * 8;
            uint32_t a[2][4];
#pragma unroll
            for (int rf = 0; rf < 2; rf++) {
                int r = rb * 32 + rf * 16 + lr;
                a[rf][0] = tf32u(sa[r * SROW + k0 + l4]);
                a[rf][1] = tf32u(sa[(r + 8) * SROW + k0 + l4]);
                a[rf][2] = tf32u(sa[r * SROW + k0 + 4 + l4]);
                a[rf][3] = tf32u(sa[(r + 8) * SROW + k0 + 4 + l4]);
            }
#pragma unroll
            for (int j = 0; j < 8; j++) {
                int cc = cb * 64 + j * 8 + lr;
                uint32_t b0 = tf32u(sbb[cc * SROW + k0 + l4]);
                uint32_t b1 = tf32u(sbb[cc * SROW + k0 + 4 + l4]);
                mma_tf32(acc[0][j], a[0][0], a[0][1], a[0][2], a[0][3], b0, b1);
                mma_tf32(acc[1][j], a[1][0], a[1][1], a[1][2], a[1][3], b0, b1);
            }
        }
        __syncthreads();    // stage (c&1) reads done before refill
        if (c + 2 < NCH) {
            issue_chunk(s, Ag, Wg, row0, c + 2, tid);
            asm volatile("cp.async.commit_group;\n");
        }
    }
}

// ---------------- kernel A: af GEMM ----------------
__global__ void __launch_bounds__(GT, 1)
af_gemm_kernel(const float* __restrict__ atom, const float* __restrict__ Wa)
{
    extern __shared__ float s[];
    const int tid = threadIdx.x;
    const int row0 = blockIdx.x * 128;
    float acc[2][8][4];
#pragma unroll
    for (int rf = 0; rf < 2; rf++)
#pragma unroll
        for (int j = 0; j < 8; j++)
#pragma unroll
            for (int q = 0; q < 4; q++) acc[rf][j][q] = 0.f;

    run_gemm(s, atom, Wa, row0, tid, acc);

    const int lane = tid & 31, w = tid >> 5;
    const int l4 = lane & 3, lr = lane >> 2;
    const int rb = w >> 2, cb = w & 3;
#pragma unroll
    for (int rf = 0; rf < 2; rf++) {
        int r0 = row0 + rb * 32 + rf * 16 + lr;
#pragma unroll
        for (int j = 0; j < 8; j++) {
            int col = cb * 64 + j * 8 + 2 * l4;
            *(float2*)(g_af + (size_t)r0 * D_ + col)
                = make_float2(acc[rf][j][0], acc[rf][j][1]);
            *(float2*)(g_af + (size_t)(r0 + 8) * D_ + col)
                = make_float2(acc[rf][j][2], acc[rf][j][3]);
        }
    }
}

// ---------------- kernel B: nf GEMM + fused epilogue ----------------
__global__ void __launch_bounds__(GT, 1)
fused_kernel(const float* __restrict__ nbr,
             const float* __restrict__ smask,
             const float* __restrict__ amask,
             const float* __restrict__ ba,
             const float* __restrict__ bn,
             const float* __restrict__ wal,
             const float* __restrict__ bal,
             const float* __restrict__ Wn,
             const float* __restrict__ gam,
             const float* __restrict__ bet,
             float* __restrict__ out)
{
    extern __shared__ float s[];
    const int tid = threadIdx.x;
    const int blk = blockIdx.x;
    const int row0 = blk * 128;

    float acc[2][8][4];
#pragma unroll
    for (int rf = 0; rf < 2; rf++)
#pragma unroll
        for (int j = 0; j < 8; j++)
#pragma unroll
            for (int q = 0; q < 4; q++) acc[rf][j][q] = 0.f;

    run_gemm(s, nbr, Wn, row0, tid, acc);
    // mainloop ends with __syncthreads(): smem free for epilogue overlay

    const int lane = tid & 31, w = tid >> 5;
    const int l4 = lane & 3, lr = lane >> 2;
    const int rb = w >> 2, cb = w & 3;

    // ---- phase 0: cooperative loads ----
    {
        float4 va = ((const float4*)(g_af + (size_t)blk * 8 * D_))[tid];
        int col = (tid * 4) & 255;
        s[E_AFB + tid * 4 + 0] = va.x + ba[col + 0];
        s[E_AFB + tid * 4 + 1] = va.y + ba[col + 1];
        s[E_AFB + tid * 4 + 2] = va.z + ba[col + 2];
        s[E_AFB + tid * 4 + 3] = va.w + ba[col + 3];
        if (tid < 64)                    ((float4*)(s + E_BN))[tid] = ((const float4*)bn)[tid];
        else if (tid < 80)               ((float4*)(s + E_WAL))[tid - 64] = ((const float4*)wal)[tid - 64];
        else if (tid >= 96 && tid < 128) ((float4*)(s + E_SMK))[tid - 96] = ((const float4*)(smask + blk * 128))[tid - 96];
        else if (tid >= 128 && tid < 160)((float4*)(s + E_AMK))[tid - 128] = ((const float4*)(amask + blk * 128))[tid - 128];
    }
    const float bal_s = bal[0];
    __syncthreads();

    // ---- phase 1: per-warp score partials (atom = rb*2+rf, head = cb) ----
#pragma unroll
    for (int rf = 0; rf < 2; rf++) {
        const int a = rb * 2 + rf;
        float s1 = 0.f, s2 = 0.f;
#pragma unroll
        for (int j = 0; j < 8; j++) {
            int c0 = cb * 64 + j * 8 + 2 * l4;
            float af0 = s[E_AFB + a * 256 + c0], af1 = s[E_AFB + a * 256 + c0 + 1];
            float b0  = s[E_BN + c0],            b1  = s[E_BN + c0 + 1];
            float w0  = s[E_WAL + (c0 & 63)],    w1  = s[E_WAL + ((c0 + 1) & 63)];
            float t;
            t = af0 + acc[rf][j][0] + b0; t = (t > 0.f) ? t : 0.2f * t; s1 = fmaf(t, w0, s1);
            t = af1 + acc[rf][j][1] + b1; t = (t > 0.f) ? t : 0.2f * t; s1 = fmaf(t, w1, s1);
            t = af0 + acc[rf][j][2] + b0; t = (t > 0.f) ? t : 0.2f * t; s2 = fmaf(t, w0, s2);
            t = af1 + acc[rf][j][3] + b1; t = (t > 0.f) ? t : 0.2f * t; s2 = fmaf(t, w1, s2);
        }
        s1 += __shfl_xor_sync(0xffffffffu, s1, 1);
        s1 += __shfl_xor_sync(0xffffffffu, s1, 2);
        s2 += __shfl_xor_sync(0xffffffffu, s2, 1);
        s2 += __shfl_xor_sync(0xffffffffu, s2, 2);
        if (l4 == 0) {
            s[E_SC + a * 64 + lr * 4 + cb]       = s1;
            s[E_SC + a * 64 + (lr + 8) * 4 + cb] = s2;
        }
    }
    __syncthreads();

    // ---- phase 2: softmax over k (32 threads: one per (atom, head)) ----
    if (tid < 32) {
        const int a = tid >> 2, h = tid & 3;
        float sc[K_], mx = -3.4e38f;
#pragma unroll
        for (int k = 0; k < K_; k++) {
            sc[k] = s[E_SC + a * 64 + k * 4 + h] + bal_s + s[E_SMK + a * 16 + k];
            mx = fmaxf(mx, sc[k]);
        }
        float ssum = 0.f;
#pragma unroll
        for (int k = 0; k < K_; k++) { sc[k] = __expf(sc[k] - mx); ssum += sc[k]; }
        float inv = 1.f / ssum;
#pragma unroll
        for (int k = 0; k < K_; k++)
            s[E_AW + a * 64 + k * 4 + h] = sc[k] * inv * s[E_AMK + a * 16 + k];
    }
    __syncthreads();

    // ---- phase 3: ctx = sum_k attw * (nf + bn) ----
#pragma unroll
    for (int rf = 0; rf < 2; rf++) {
        const int a = rb * 2 + rf;
        const float aw1 = s[E_AW + a * 64 + lr * 4 + cb];
        const float aw2 = s[E_AW + a * 64 + (lr + 8) * 4 + cb];
#pragma unroll
        for (int j = 0; j < 8; j++) {
            int c0 = cb * 64 + j * 8 + 2 * l4;
            float b0 = s[E_BN + c0], b1 = s[E_BN + c0 + 1];
            float c0v = aw1 * (acc[rf][j][0] + b0) + aw2 * (acc[rf][j][2] + b0);
            float c1v = aw1 * (acc[rf][j][1] + b1) + aw2 * (acc[rf][j][3] + b1);
#pragma unroll
            for (int off = 4; off <= 16; off <<= 1) {
                c0v += __shfl_xor_sync(0xffffffffu, c0v, off);
                c1v += __shfl_xor_sync(0xffffffffu, c1v, off);
            }
            if (lr == 0)
                *(float2*)(s + E_CTX + a * 264 + c0) = make_float2(c0v, c1v);
        }
    }
    __syncthreads();

    // ---- phase 4: LayerNorm + store (half ah handles 4 atoms) ----
    const int dd = tid & 255;
    const int ah = tid >> 8;
    const int wih = (tid & 255) >> 5;
    const float g_d  = gam[dd];
    const float be_d = bet[dd];
#pragma unroll
    for (int i = 0; i < 4; i++) {
        const int a = ah * 4 + i;
        float ctx = s[E_CTX + a * 264 + dd];
        float s1 = ctx, s2 = ctx * ctx;
#pragma unroll
        for (int off = 16; off; off >>= 1) {
            s1 += __shfl_xor_sync(0xffffffffu, s1, off);
            s2 += __shfl_xor_sync(0xffffffffu, s2, off);
        }
        if (lane == 0) {
            s[E_LN + ah * 16 + wih] = s1;
            s[E_LN + ah * 16 + 8 + wih] = s2;
        }
        __syncthreads();
        float S1 = 0.f, S2 = 0.f;
#pragma unroll
        for (int q = 0; q < 8; q++) {
            S1 += s[E_LN + ah * 16 + q];
            S2 += s[E_LN + ah * 16 + 8 + q];
        }
        float mu  = S1 * (1.f / 256.f);
        float var = S2 * (1.f / 256.f) - mu * mu;
        float o = (ctx - mu) * rsqrtf(var + 1e-5f) * g_d + be_d;
        out[(size_t)(blk * 8 + a) * D_ + dd] = o;
        __syncthreads();
    }
}

extern "C" void kernel_launch(void* const* d_in, const int* in_sizes, int n_in,
                              void* d_out, int out_size)
{
    const float* atom_feat = (const float*)d_in[0];
    const float* nbr_feat  = (const float*)d_in[1];
    const float* smask     = (const float*)d_in[2];
    const float* amask     = (const float*)d_in[3];
    const float* Wa        = (const float*)d_in[4];
    const float* ba        = (const float*)d_in[5];
    const float* Wn        = (const float*)d_in[6];
    const float* bn        = (const float*)d_in[7];
    const float* wal       = (const float*)d_in[8];
    const float* bal       = (const float*)d_in[9];
    const float* gam       = (const float*)d_in[10];
    const float* bet       = (const float*)d_in[11];
    float* out = (float*)d_out;

    cudaFuncSetAttribute(af_gemm_kernel,
                         cudaFuncAttributeMaxDynamicSharedMemorySize,
                         GSMEM * (int)sizeof(float));
    cudaFuncSetAttribute(fused_kernel,
                         cudaFuncAttributeMaxDynamicSharedMemorySize,
                         GSMEM * (int)sizeof(float));

    af_gemm_kernel<<<AF_TILES, GT, GSMEM * sizeof(float)>>>(atom_feat, Wa);
    fused_kernel<<<NF_TILES, GT, GSMEM * sizeof(float)>>>(
        nbr_feat, smask, amask, ba, bn, wal, bal, Wn, gam, bet, out);
}